// round 6
// baseline (speedup 1.0000x reference)
#include <cuda_runtime.h>
#include <cuda_bf16.h>
#include <cstdint>
#include <math.h>

// ---------------- problem constants ----------------
#define BATCH   2
#define LSEQ    2048
#define DM      1024          // d_model
#define DIP     4384          // d_in_proj
#define DIPPAD  4480          // padded to 35*128
#define DSSM    2048          // d_inner / d_ssm
#define CONVD   2304          // conv dim
#define NH      32            // heads
#define DH      64            // head dim (P)
#define DS      128           // d_state (N)
#define CH      128           // chunk size (math-equivalent re-chunking)
#define NC      (LSEQ / CH)   // 16 chunks per batch
#define ROWS    (BATCH * LSEQ)  // 4096
#define ZOFF    0
#define XBCOFF  2048
#define DTOFF   4352
#define XOFF    0
#define BOFF    2048
#define COFF    2176

// ---------------- scratch (no allocations allowed) ----------------
__device__ float g_zx[ROWS * DIP];
__device__ float g_xc[ROWS * CONVD];
__device__ float g_dtT[BATCH * NC * NH * CH];
__device__ float g_cumT[BATCH * NC * NH * CH];
__device__ float g_cdecay[BATCH * NC * NH];
__device__ float g_CB[BATCH * NC * CH * CH];
__device__ float g_S[BATCH * NC * NH * DH * DS];
__device__ float g_prev[BATCH * NC * NH * DH * DS];
__device__ float g_y[ROWS * DSSM];

// bf16 hi/lo split buffers for tensor-core GEMMs
__device__ __nv_bfloat16 g_uhi[ROWS * DM],   g_ulo[ROWS * DM];
__device__ __nv_bfloat16 g_w1hi[DIPPAD * DM], g_w1lo[DIPPAD * DM];
__device__ __nv_bfloat16 g_yhi[ROWS * DSSM], g_ylo[ROWS * DSSM];
__device__ __nv_bfloat16 g_w2hi[DM * DSSM],  g_w2lo[DM * DSSM];

// ---------------- PTX helpers ----------------
__device__ __forceinline__ uint32_t smem_u32(const void* p) {
    return (uint32_t)__cvta_generic_to_shared(p);
}
#define LDMX4(r0,r1,r2,r3,addr) \
    asm volatile("ldmatrix.sync.aligned.m8n8.x4.shared.b16 {%0,%1,%2,%3}, [%4];" \
                 : "=r"(r0),"=r"(r1),"=r"(r2),"=r"(r3) : "r"(addr))
#define MMA16816(d,a,b) \
    asm volatile("mma.sync.aligned.m16n8k16.row.col.f32.bf16.bf16.f32 " \
                 "{%0,%1,%2,%3},{%4,%5,%6,%7},{%8,%9},{%0,%1,%2,%3};" \
                 : "+f"((d)[0]),"+f"((d)[1]),"+f"((d)[2]),"+f"((d)[3]) \
                 : "r"((a)[0]),"r"((a)[1]),"r"((a)[2]),"r"((a)[3]),"r"((b)[0]),"r"((b)[1]))
#define CPASYNC16(s,g) \
    asm volatile("cp.async.cg.shared.global [%0], [%1], 16;" :: "r"(s),"l"(g))
#define CP_COMMIT() asm volatile("cp.async.commit_group;")

// ---------------- fp32 -> bf16 hi/lo split conversion ----------------
__global__ __launch_bounds__(256)
void cvt_split(const float* __restrict__ X, __nv_bfloat16* __restrict__ hi,
               __nv_bfloat16* __restrict__ lo, long nquad, long nquad_src)
{
    long q = (long)blockIdx.x * 256 + threadIdx.x;
    if (q >= nquad) return;
    float4 v = make_float4(0.f, 0.f, 0.f, 0.f);
    if (q < nquad_src) v = *(const float4*)&X[q * 4];
    __nv_bfloat16 h0 = __float2bfloat16(v.x);
    __nv_bfloat16 h1 = __float2bfloat16(v.y);
    __nv_bfloat16 h2 = __float2bfloat16(v.z);
    __nv_bfloat16 h3 = __float2bfloat16(v.w);
    __nv_bfloat16 l0 = __float2bfloat16(v.x - __bfloat162float(h0));
    __nv_bfloat16 l1 = __float2bfloat16(v.y - __bfloat162float(h1));
    __nv_bfloat16 l2 = __float2bfloat16(v.z - __bfloat162float(h2));
    __nv_bfloat16 l3 = __float2bfloat16(v.w - __bfloat162float(h3));
    __nv_bfloat162* hp = (__nv_bfloat162*)&hi[q * 4];
    __nv_bfloat162* lp = (__nv_bfloat162*)&lo[q * 4];
    hp[0] = __nv_bfloat162(h0, h1); hp[1] = __nv_bfloat162(h2, h3);
    lp[0] = __nv_bfloat162(l0, l1); lp[1] = __nv_bfloat162(l2, l3);
}

// ---------------- bf16x3 tensor-core GEMM, 256x128 tile, 3-stage pipeline ----------------
// A [M,K] row-major (hi/lo), B [Npad,K] row-major (hi/lo), C fp32 [M,ldc], store n<N.
// Block tile 256x128, warp tile 64x64 (8 warps, 4x2 grid), BK=32.
#define SM_STRIDE 40                    // bf16 elems per smem row (80B)
#define OFF_ALO   10240                 // 256*40
#define OFF_BHI   20480
#define OFF_BLO   25600                 // 20480 + 128*40
#define STAGE_E   30720                 // elems per stage
#define STAGE_B   (STAGE_E * 2)         // bytes per stage (61440)
#define SMEM_TOT  (3 * STAGE_B)         // 184320 B

__global__ __launch_bounds__(256, 1)
void gemm_bf3(const __nv_bfloat16* __restrict__ Ahi, const __nv_bfloat16* __restrict__ Alo,
              const __nv_bfloat16* __restrict__ Bhi, const __nv_bfloat16* __restrict__ Blo,
              float* __restrict__ C, int M, int N, int K, int ldc)
{
    extern __shared__ __nv_bfloat16 sm[];
    const uint32_t sbase = smem_u32(sm);
    const int tid = threadIdx.x;
    const int lane = tid & 31, wid = tid >> 5;
    const int wr = wid & 3, wc = wid >> 2;       // 4x2 warp grid -> 64x64 per warp
    const int row0 = blockIdx.y * 256;
    const int col0 = blockIdx.x * 128;

    float acc[4][8][4];
#pragma unroll
    for (int i = 0; i < 4; i++)
#pragma unroll
        for (int j = 0; j < 8; j++)
#pragma unroll
            for (int k = 0; k < 4; k++) acc[i][j][k] = 0.f;

    const int nt = K >> 5;

    auto issue = [&](int kt, int stage) {
        uint32_t sb = sbase + stage * STAGE_B;
        // A hi/lo: 1024 chunks each; 4 per thread
#pragma unroll
        for (int k = 0; k < 4; k++) {
            int id = tid + k * 256;
            int row = id >> 2, c8 = (id & 3) * 8;
            CPASYNC16(sb + (row * SM_STRIDE + c8) * 2,
                      Ahi + (long)(row0 + row) * K + kt + c8);
            CPASYNC16(sb + (OFF_ALO + row * SM_STRIDE + c8) * 2,
                      Alo + (long)(row0 + row) * K + kt + c8);
        }
        // B hi/lo: 512 chunks each; 2 per thread
#pragma unroll
        for (int k = 0; k < 2; k++) {
            int id = tid + k * 256;
            int row = id >> 2, c8 = (id & 3) * 8;
            CPASYNC16(sb + (OFF_BHI + row * SM_STRIDE + c8) * 2,
                      Bhi + (long)(col0 + row) * K + kt + c8);
            CPASYNC16(sb + (OFF_BLO + row * SM_STRIDE + c8) * 2,
                      Blo + (long)(col0 + row) * K + kt + c8);
        }
        CP_COMMIT();
    };

    issue(0, 0);
    if (nt > 1) issue(32, 1);

    for (int it = 0; it < nt; it++) {
        if (it + 1 < nt) {
            asm volatile("cp.async.wait_group 1;");
        } else {
            asm volatile("cp.async.wait_group 0;");
        }
        __syncthreads();
        if (it + 2 < nt) issue((it + 2) << 5, (it + 2) % 3);

        uint32_t sb = sbase + (it % 3) * STAGE_B;
#pragma unroll
        for (int kk = 0; kk < 32; kk += 16) {
            uint32_t ah[4][4], al[4][4];
#pragma unroll
            for (int mi = 0; mi < 4; mi++) {
                int arow = wr * 64 + mi * 16 + (lane & 15);
                int acol = kk + (lane >> 4) * 8;
                uint32_t ad = sb + (arow * SM_STRIDE + acol) * 2;
                LDMX4(ah[mi][0], ah[mi][1], ah[mi][2], ah[mi][3], ad);
                LDMX4(al[mi][0], al[mi][1], al[mi][2], al[mi][3], ad + OFF_ALO * 2);
            }
#pragma unroll
            for (int half = 0; half < 4; half++) {
                uint32_t bh[2][2], bl[2][2];
                int brow = wc * 64 + half * 16 + (lane & 7) + ((lane >> 4) & 1) * 8;
                int bcol = kk + ((lane >> 3) & 1) * 8;
                uint32_t bd = sb + (OFF_BHI + brow * SM_STRIDE + bcol) * 2;
                uint32_t t0, t1, t2, t3;
                LDMX4(t0, t1, t2, t3, bd);
                bh[0][0] = t0; bh[0][1] = t1; bh[1][0] = t2; bh[1][1] = t3;
                LDMX4(t0, t1, t2, t3, bd + (OFF_BLO - OFF_BHI) * 2);
                bl[0][0] = t0; bl[0][1] = t1; bl[1][0] = t2; bl[1][1] = t3;
#pragma unroll
                for (int mi = 0; mi < 4; mi++)
#pragma unroll
                    for (int jj = 0; jj < 2; jj++) {
                        int nj = half * 2 + jj;
                        MMA16816(acc[mi][nj], ah[mi], bh[jj]);
                        MMA16816(acc[mi][nj], ah[mi], bl[jj]);
                        MMA16816(acc[mi][nj], al[mi], bh[jj]);
                    }
            }
        }
        __syncthreads();
    }

    // epilogue
#pragma unroll
    for (int mi = 0; mi < 4; mi++) {
        int r = row0 + wr * 64 + mi * 16 + (lane >> 2);
#pragma unroll
        for (int nj = 0; nj < 8; nj++) {
            int cc = col0 + wc * 64 + nj * 8 + (lane & 3) * 2;
            if (cc < N) {
                *(float2*)&C[(long)r * ldc + cc] = make_float2(acc[mi][nj][0], acc[mi][nj][1]);
                *(float2*)&C[(long)(r + 8) * ldc + cc] = make_float2(acc[mi][nj][2], acc[mi][nj][3]);
            }
        }
    }
}

// ---------------- generic NT SGEMM (small batched CB gemm) ----------------
__global__ __launch_bounds__(256)
void sgemm_nt(const float* __restrict__ A, const float* __restrict__ B,
              float* __restrict__ C, int M, int Nn, int K,
              int lda, int ldb, int ldc,
              long sA, long sB, long sC)
{
    __shared__ float As[16][132];
    __shared__ float Bs[16][132];
    A += (long)blockIdx.z * sA;
    B += (long)blockIdx.z * sB;
    C += (long)blockIdx.z * sC;

    const int tid = threadIdx.x;
    const int tx = tid & 15, ty = tid >> 4;
    const int row0 = blockIdx.y * 128;
    const int col0 = blockIdx.x * 128;
    const int lr = tid >> 2;
    const int lc = (tid & 3) * 4;

    float acc[8][8];
#pragma unroll
    for (int i = 0; i < 8; i++)
#pragma unroll
        for (int j = 0; j < 8; j++) acc[i][j] = 0.f;

    for (int kt = 0; kt < K; kt += 16) {
#pragma unroll
        for (int r = 0; r < 2; r++) {
            int row = lr + r * 64;
            float4 v = *(const float4*)&A[(long)(row0 + row) * lda + kt + lc];
            As[lc + 0][row] = v.x; As[lc + 1][row] = v.y;
            As[lc + 2][row] = v.z; As[lc + 3][row] = v.w;
        }
#pragma unroll
        for (int r = 0; r < 2; r++) {
            int col = lr + r * 64;
            int n = col0 + col;
            float4 v = make_float4(0.f, 0.f, 0.f, 0.f);
            if (n < Nn) v = *(const float4*)&B[(long)n * ldb + kt + lc];
            Bs[lc + 0][col] = v.x; Bs[lc + 1][col] = v.y;
            Bs[lc + 2][col] = v.z; Bs[lc + 3][col] = v.w;
        }
        __syncthreads();
#pragma unroll
        for (int k = 0; k < 16; k++) {
            float a[8], b[8];
            *(float4*)&a[0] = *(float4*)&As[k][ty * 8];
            *(float4*)&a[4] = *(float4*)&As[k][ty * 8 + 4];
            *(float4*)&b[0] = *(float4*)&Bs[k][tx * 8];
            *(float4*)&b[4] = *(float4*)&Bs[k][tx * 8 + 4];
#pragma unroll
            for (int i = 0; i < 8; i++)
#pragma unroll
                for (int j = 0; j < 8; j++) acc[i][j] += a[i] * b[j];
        }
        __syncthreads();
    }
#pragma unroll
    for (int i = 0; i < 8; i++) {
        int row = row0 + ty * 8 + i;
#pragma unroll
        for (int j4 = 0; j4 < 8; j4 += 4) {
            int n = col0 + tx * 8 + j4;
            if (n < Nn) {
                float4 o = make_float4(acc[i][j4], acc[i][j4+1], acc[i][j4+2], acc[i][j4+3]);
                *(float4*)&C[(long)row * ldc + n] = o;
            }
        }
    }
}

// ---------------- conv1d (depthwise, causal, k=4) + silu — smem tiled ----------------
__global__ __launch_bounds__(256)
void conv_silu_kernel(const float* __restrict__ conv_w, const float* __restrict__ conv_b)
{
    __shared__ float t[35][256];
    int tid = threadIdx.x;
    int col = blockIdx.x * 256 + tid;
    int rowstart = blockIdx.y * 32;
    int l0 = rowstart & (LSEQ - 1);

#pragma unroll
    for (int r = 0; r < 35; r++) {
        int l = l0 - 3 + r;
        float v = 0.f;
        if (l >= 0) v = g_zx[(long)(rowstart - 3 + r) * DIP + XBCOFF + col];
        t[r][tid] = v;
    }
    __syncthreads();

    float w0 = conv_w[col * 4 + 0], w1 = conv_w[col * 4 + 1];
    float w2 = conv_w[col * 4 + 2], w3 = conv_w[col * 4 + 3];
    float bb = conv_b[col];
#pragma unroll
    for (int r = 0; r < 32; r++) {
        float acc = bb + t[r][tid] * w0 + t[r + 1][tid] * w1
                       + t[r + 2][tid] * w2 + t[r + 3][tid] * w3;
        float s = acc / (1.f + __expf(-acc));
        g_xc[(long)(rowstart + r) * CONVD + col] = s;
    }
}

// ---------------- dt = softplus(dt_raw + bias); per-chunk cumsum — parallel ----------------
__global__ __launch_bounds__(256)
void dtcum_kernel(const float* __restrict__ dt_bias, const float* __restrict__ A_log)
{
    __shared__ float sdt[CH][33];
    __shared__ float scum[CH][33];
    int bc = blockIdx.x;
    int b = bc / NC, c = bc % NC;
    int tid = threadIdx.x;
    int rowbase = b * LSEQ + c * CH;

    for (int i = tid; i < CH * NH; i += 256) {
        int l = i >> 5, h = i & 31;
        float raw = g_zx[(long)(rowbase + l) * DIP + DTOFF + h] + dt_bias[h];
        float dtv = (raw > 20.f) ? raw : log1pf(expf(raw));
        sdt[l][h] = dtv;
    }
    __syncthreads();

    if (tid < NH) {
        float Ah = -expf(A_log[tid]);
        float cum = 0.f;
#pragma unroll
        for (int l = 0; l < CH; l++) {
            cum += sdt[l][tid] * Ah;
            scum[l][tid] = cum;
        }
        g_cdecay[bc * NH + tid] = expf(cum);
    }
    __syncthreads();

    for (int i = tid; i < CH * NH; i += 256) {
        int h = i >> 7, l = i & 127;
        g_dtT[(bc * NH + h) * CH + l] = sdt[l][h];
        g_cumT[(bc * NH + h) * CH + l] = scum[l][h];
    }
}

// ---------------- per-chunk end states ----------------
__global__ __launch_bounds__(256)
void states_kernel()
{
    int bch = blockIdx.x;
    int h = bch % NH;
    int bc = bch / NH;
    int b = bc / NC, c = bc % NC;
    int tid = threadIdx.x;
    int tx = tid & 15, ty = tid >> 4;

    __shared__ float ws[CH];
    __shared__ float Xs[16][68];
    __shared__ float Bs2[16][132];

    int base = bch * CH;
    if (tid < CH) {
        float clast = g_cumT[base + CH - 1];
        ws[tid] = g_dtT[base + tid] * __expf(clast - g_cumT[base + tid]);
    }
    __syncthreads();

    float acc[4][8];
#pragma unroll
    for (int i = 0; i < 4; i++)
#pragma unroll
        for (int j = 0; j < 8; j++) acc[i][j] = 0.f;

    int rowbase = b * LSEQ + c * CH;
    for (int kt = 0; kt < CH; kt += 16) {
        {
            int si = tid >> 4, pj = (tid & 15) * 4;
            float4 v = *(const float4*)&g_xc[(long)(rowbase + kt + si) * CONVD + XOFF + h * DH + pj];
            float w = ws[kt + si];
            Xs[si][pj + 0] = v.x * w; Xs[si][pj + 1] = v.y * w;
            Xs[si][pj + 2] = v.z * w; Xs[si][pj + 3] = v.w * w;
        }
        {
            int si = tid >> 4, nj = (tid & 15) * 8;
            const float* p = &g_xc[(long)(rowbase + kt + si) * CONVD + BOFF + nj];
            float4 v0 = *(const float4*)&p[0];
            float4 v1 = *(const float4*)&p[4];
            Bs2[si][nj + 0] = v0.x; Bs2[si][nj + 1] = v0.y; Bs2[si][nj + 2] = v0.z; Bs2[si][nj + 3] = v0.w;
            Bs2[si][nj + 4] = v1.x; Bs2[si][nj + 5] = v1.y; Bs2[si][nj + 6] = v1.z; Bs2[si][nj + 7] = v1.w;
        }
        __syncthreads();
#pragma unroll
        for (int k = 0; k < 16; k++) {
            float a[4], bb[8];
            *(float4*)&a[0]  = *(float4*)&Xs[k][ty * 4];
            *(float4*)&bb[0] = *(float4*)&Bs2[k][tx * 8];
            *(float4*)&bb[4] = *(float4*)&Bs2[k][tx * 8 + 4];
#pragma unroll
            for (int i = 0; i < 4; i++)
#pragma unroll
                for (int j = 0; j < 8; j++) acc[i][j] += a[i] * bb[j];
        }
        __syncthreads();
    }
    float* Sp = g_S + (long)bch * DH * DS;
#pragma unroll
    for (int i = 0; i < 4; i++) {
        int p = ty * 4 + i;
#pragma unroll
        for (int j4 = 0; j4 < 8; j4 += 4) {
            float4 o = make_float4(acc[i][j4], acc[i][j4+1], acc[i][j4+2], acc[i][j4+3]);
            *(float4*)&Sp[p * DS + tx * 8 + j4] = o;
        }
    }
}

// ---------------- inter-chunk recurrence — split 8x for parallelism ----------------
__global__ __launch_bounds__(256)
void scan_kernel()
{
    int bh = blockIdx.x >> 3;
    int slice = blockIdx.x & 7;
    int b = bh >> 5, h = bh & 31;
    int off = slice * 1024 + threadIdx.x * 4;
    float4 carry = make_float4(0.f, 0.f, 0.f, 0.f);
    for (int c = 0; c < NC; c++) {
        int bch = (b * NC + c) * NH + h;
        float d = g_cdecay[bch];
        long idx = (long)bch * (DH * DS) + off;
        float4 s = *(const float4*)&g_S[idx];
        *(float4*)&g_prev[idx] = carry;
        carry.x = carry.x * d + s.x;
        carry.y = carry.y * d + s.y;
        carry.z = carry.z * d + s.z;
        carry.w = carry.w * d + s.w;
    }
}

// ---------------- Y = intra + inter + D*x (causal tile skip in phase 1) ----------------
__global__ __launch_bounds__(256)
void y_kernel(const float* __restrict__ Dparam)
{
    int bch = blockIdx.x;
    int h = bch % NH;
    int bc = bch / NH;
    int b = bc / NC, c = bc % NC;
    int tid = threadIdx.x;
    int tx = tid & 15, ty = tid >> 4;

    __shared__ float cl[CH], dts[CH], Fg[CH], El[CH];
    __shared__ float As[16][132];
    __shared__ float xs[16][68];

    int base = bch * CH;
    if (tid < CH) {
        float cv = g_cumT[base + tid];
        cl[tid] = cv;
        dts[tid] = g_dtT[base + tid];
        El[tid] = __expf(cv);
    }
    __syncthreads();
    if (tid < CH) Fg[tid] = __expf(cl[tid] - cl[tid & ~7]);
    __syncthreads();

    float acc[8][4];
#pragma unroll
    for (int i = 0; i < 8; i++)
#pragma unroll
        for (int j = 0; j < 4; j++) acc[i][j] = 0.f;

    const float* CBp = g_CB + (long)bc * CH * CH;
    int rowbase = b * LSEQ + c * CH;

    int s16 = tid & 15;
    int l0 = (tid >> 4) * 8;
    for (int kt = 0; kt < CH; kt += 16) {
        int sg = kt + s16;
        float e0 = __expf(fminf(cl[l0] - cl[sg], 85.f)) * dts[sg];
#pragma unroll
        for (int i = 0; i < 8; i++) {
            int lg = l0 + i;
            float v = (sg <= lg) ? CBp[lg * CH + sg] * Fg[lg] * e0 : 0.f;
            As[s16][lg] = v;
        }
        {
            int si = tid >> 4, pj = (tid & 15) * 4;
            float4 v = *(const float4*)&g_xc[(long)(rowbase + kt + si) * CONVD + XOFF + h * DH + pj];
            *(float4*)&xs[si][pj] = v;
        }
        __syncthreads();
        if (kt <= l0 + 7) {
#pragma unroll
            for (int k = 0; k < 16; k++) {
                float a[8], bb[4];
                *(float4*)&a[0] = *(float4*)&As[k][ty * 8];
                *(float4*)&a[4] = *(float4*)&As[k][ty * 8 + 4];
                *(float4*)&bb[0] = *(float4*)&xs[k][tx * 4];
#pragma unroll
                for (int i = 0; i < 8; i++)
#pragma unroll
                    for (int j = 0; j < 4; j++) acc[i][j] += a[i] * bb[j];
            }
        }
        __syncthreads();
    }

    const float* Pv = g_prev + (long)bch * DH * DS;
    int lrow = tid >> 1;
    int half = tid & 1;
    for (int nt = 0; nt < DS; nt += 16) {
        {
            float el = El[lrow];
            const float* p = &g_xc[(long)(rowbase + lrow) * CONVD + COFF + nt + half * 8];
            float4 v0 = *(const float4*)&p[0];
            float4 v1 = *(const float4*)&p[4];
            int nb = half * 8;
            As[nb + 0][lrow] = v0.x * el; As[nb + 1][lrow] = v0.y * el;
            As[nb + 2][lrow] = v0.z * el; As[nb + 3][lrow] = v0.w * el;
            As[nb + 4][lrow] = v1.x * el; As[nb + 5][lrow] = v1.y * el;
            As[nb + 6][lrow] = v1.z * el; As[nb + 7][lrow] = v1.w * el;
        }
        {
            int p = tid >> 2, n4 = (tid & 3) * 4;
            float4 v = *(const float4*)&Pv[p * DS + nt + n4];
            xs[n4 + 0][p] = v.x; xs[n4 + 1][p] = v.y;
            xs[n4 + 2][p] = v.z; xs[n4 + 3][p] = v.w;
        }
        __syncthreads();
#pragma unroll
        for (int k = 0; k < 16; k++) {
            float a[8], bb[4];
            *(float4*)&a[0] = *(float4*)&As[k][ty * 8];
            *(float4*)&a[4] = *(float4*)&As[k][ty * 8 + 4];
            *(float4*)&bb[0] = *(float4*)&xs[k][tx * 4];
#pragma unroll
            for (int i = 0; i < 8; i++)
#pragma unroll
                for (int j = 0; j < 4; j++) acc[i][j] += a[i] * bb[j];
        }
        __syncthreads();
    }

    float Dh = Dparam[h];
#pragma unroll
    for (int i = 0; i < 8; i++) {
        int lg = ty * 8 + i;
        int row = rowbase + lg;
        float4 xv = *(const float4*)&g_xc[(long)row * CONVD + XOFF + h * DH + tx * 4];
        float4 o;
        o.x = acc[i][0] + Dh * xv.x;
        o.y = acc[i][1] + Dh * xv.y;
        o.z = acc[i][2] + Dh * xv.z;
        o.w = acc[i][3] + Dh * xv.w;
        *(float4*)&g_y[(long)row * DSSM + h * DH + tx * 4] = o;
    }
}

// ---------------- gate (silu(z)) + RMSNorm, emits bf16 hi/lo directly ----------------
__global__ __launch_bounds__(256)
void gatenorm_kernel(const float* __restrict__ norm_w)
{
    int row = blockIdx.x;
    int tid = threadIdx.x;
    float v[8];
    float ss = 0.f;
#pragma unroll
    for (int j = 0; j < 8; j++) {
        int cidx = tid + j * 256;
        float y = g_y[(long)row * DSSM + cidx];
        float z = g_zx[(long)row * DIP + ZOFF + cidx];
        float g = z / (1.f + __expf(-z));
        float yg = y * g;
        v[j] = yg;
        ss += yg * yg;
    }
#pragma unroll
    for (int o = 16; o > 0; o >>= 1) ss += __shfl_xor_sync(0xffffffffu, ss, o);
    __shared__ float red[8];
    __shared__ float rinv;
    if ((tid & 31) == 0) red[tid >> 5] = ss;
    __syncthreads();
    if (tid == 0) {
        float t = 0.f;
#pragma unroll
        for (int i = 0; i < 8; i++) t += red[i];
        rinv = rsqrtf(t / (float)DSSM + 1e-5f);
    }
    __syncthreads();
    float r = rinv;
#pragma unroll
    for (int j = 0; j < 8; j++) {
        int cidx = tid + j * 256;
        float val = v[j] * r * norm_w[cidx];
        __nv_bfloat16 hh = __float2bfloat16(val);
        __nv_bfloat16 ll = __float2bfloat16(val - __bfloat162float(hh));
        g_yhi[(long)row * DSSM + cidx] = hh;
        g_ylo[(long)row * DSSM + cidx] = ll;
    }
}

// ---------------- host launcher ----------------
extern "C" void kernel_launch(void* const* d_in, const int* in_sizes, int n_in,
                              void* d_out, int out_size)
{
    const float* u       = (const float*)d_in[0];
    const float* W_in    = (const float*)d_in[1];
    const float* conv_w  = (const float*)d_in[2];
    const float* conv_b  = (const float*)d_in[3];
    const float* dt_bias = (const float*)d_in[4];
    const float* A_log   = (const float*)d_in[5];
    const float* Dp      = (const float*)d_in[6];
    const float* norm_w  = (const float*)d_in[7];
    const float* W_out   = (const float*)d_in[8];
    float* out = (float*)d_out;

    float *p_zx, *p_xc, *p_CB;
    cudaGetSymbolAddress((void**)&p_zx, g_zx);
    cudaGetSymbolAddress((void**)&p_xc, g_xc);
    cudaGetSymbolAddress((void**)&p_CB, g_CB);
    __nv_bfloat16 *p_uhi, *p_ulo, *p_w1hi, *p_w1lo, *p_yhi, *p_ylo, *p_w2hi, *p_w2lo;
    cudaGetSymbolAddress((void**)&p_uhi, g_uhi);
    cudaGetSymbolAddress((void**)&p_ulo, g_ulo);
    cudaGetSymbolAddress((void**)&p_w1hi, g_w1hi);
    cudaGetSymbolAddress((void**)&p_w1lo, g_w1lo);
    cudaGetSymbolAddress((void**)&p_yhi, g_yhi);
    cudaGetSymbolAddress((void**)&p_ylo, g_ylo);
    cudaGetSymbolAddress((void**)&p_w2hi, g_w2hi);
    cudaGetSymbolAddress((void**)&p_w2lo, g_w2lo);

    static int smem_set = 0;
    if (!smem_set) {
        cudaFuncSetAttribute(gemm_bf3, cudaFuncAttributeMaxDynamicSharedMemorySize, SMEM_TOT);
        smem_set = 1;
    }

    // 0) bf16 hi/lo conversions of u, W_in (padded), W_out
    {
        long nq = (long)ROWS * DM / 4;
        cvt_split<<<(nq + 255) / 256, 256>>>(u, p_uhi, p_ulo, nq, nq);
    }
    {
        long nq = (long)DIPPAD * DM / 4, ns = (long)DIP * DM / 4;
        cvt_split<<<(nq + 255) / 256, 256>>>(W_in, p_w1hi, p_w1lo, nq, ns);
    }
    {
        long nq = (long)DM * DSSM / 4;
        cvt_split<<<(nq + 255) / 256, 256>>>(W_out, p_w2hi, p_w2lo, nq, nq);
    }

    // 1) in_proj (tensor cores): zxbcdt = u @ W_in^T
    gemm_bf3<<<dim3(DIPPAD / 128, ROWS / 256), 256, SMEM_TOT>>>(
        p_uhi, p_ulo, p_w1hi, p_w1lo, p_zx, ROWS, DIP, DM, DIP);

    // 2) conv + silu (tiled)
    conv_silu_kernel<<<dim3(CONVD / 256, ROWS / 32), 256>>>(conv_w, conv_b);

    // 3) dt / cumsum (parallel per-chunk)
    dtcum_kernel<<<BATCH * NC, 256>>>(dt_bias, A_log);

    // 4) CB = C @ B^T per chunk
    sgemm_nt<<<dim3(1, 1, BATCH * NC), 256>>>(
        p_xc + COFF, p_xc + BOFF, p_CB, CH, CH, DS,
        CONVD, CONVD, CH,
        (long)CH * CONVD, (long)CH * CONVD, (long)CH * CH);

    // 5) per-chunk end states
    states_kernel<<<BATCH * NC * NH, 256>>>();

    // 6) inter-chunk scan (8-way split)
    scan_kernel<<<BATCH * NH * 8, 256>>>();

    // 7) Y = intra + inter + D*x
    y_kernel<<<BATCH * NC * NH, 256>>>(Dp);

    // 8) gate + RMSNorm (emits yhi/ylo)
    gatenorm_kernel<<<ROWS, 256>>>(norm_w);

    // 9) out_proj on tensor cores
    gemm_bf3<<<dim3(DM / 128, ROWS / 256), 256, SMEM_TOT>>>(
        p_yhi, p_ylo, p_w2hi, p_w2lo, out, ROWS, DM, DSSM, DM);

    (void)in_sizes; (void)n_in; (void)out_size;
}

// round 8
// speedup vs baseline: 1.0966x; 1.0966x over previous
#include <cuda_runtime.h>
#include <cuda_bf16.h>
#include <cstdint>
#include <math.h>

// ---------------- problem constants ----------------
#define BATCH   2
#define LSEQ    2048
#define DM      1024
#define DIP     4384
#define DIPPAD  4480
#define DSSM    2048
#define CONVD   2304
#define NH      32
#define DH      64
#define DS      128
#define CH      128
#define NC      (LSEQ / CH)
#define ROWS    (BATCH * LSEQ)
#define ZOFF    0
#define XBCOFF  2048
#define DTOFF   4352
#define XOFF    0
#define BOFF    2048
#define COFF    2176

// ---------------- scratch ----------------
__device__ float g_zx[ROWS * DIP];
__device__ float g_xc[ROWS * CONVD];
__device__ __nv_bfloat16 g_xcb[ROWS * CONVD];   // bf16 copy of conv output
__device__ float g_dtT[BATCH * NC * NH * CH];
__device__ float g_cumT[BATCH * NC * NH * CH];
__device__ float g_cdecay[BATCH * NC * NH];
__device__ float g_CB[BATCH * NC * CH * CH];
__device__ float g_S[BATCH * NC * NH * DH * DS];
__device__ float g_prev[BATCH * NC * NH * DH * DS];
__device__ float g_y[ROWS * DSSM];

__device__ __nv_bfloat16 g_uhi[ROWS * DM],   g_ulo[ROWS * DM];
__device__ __nv_bfloat16 g_w1hi[DIPPAD * DM], g_w1lo[DIPPAD * DM];
__device__ __nv_bfloat16 g_yhi[ROWS * DSSM], g_ylo[ROWS * DSSM];
__device__ __nv_bfloat16 g_w2hi[DM * DSSM],  g_w2lo[DM * DSSM];

// ---------------- PTX helpers ----------------
__device__ __forceinline__ uint32_t smem_u32(const void* p) {
    return (uint32_t)__cvta_generic_to_shared(p);
}
#define LDMX4(r0,r1,r2,r3,addr) \
    asm volatile("ldmatrix.sync.aligned.m8n8.x4.shared.b16 {%0,%1,%2,%3}, [%4];" \
                 : "=r"(r0),"=r"(r1),"=r"(r2),"=r"(r3) : "r"(addr))
#define LDMX4T(r0,r1,r2,r3,addr) \
    asm volatile("ldmatrix.sync.aligned.m8n8.x4.trans.shared.b16 {%0,%1,%2,%3}, [%4];" \
                 : "=r"(r0),"=r"(r1),"=r"(r2),"=r"(r3) : "r"(addr))
#define MMA16816(d,a,b) \
    asm volatile("mma.sync.aligned.m16n8k16.row.col.f32.bf16.bf16.f32 " \
                 "{%0,%1,%2,%3},{%4,%5,%6,%7},{%8,%9},{%0,%1,%2,%3};" \
                 : "+f"((d)[0]),"+f"((d)[1]),"+f"((d)[2]),"+f"((d)[3]) \
                 : "r"((a)[0]),"r"((a)[1]),"r"((a)[2]),"r"((a)[3]),"r"((b)[0]),"r"((b)[1]))
#define CPASYNC16(s,g) \
    asm volatile("cp.async.cg.shared.global [%0], [%1], 16;" :: "r"(s),"l"(g))
#define CP_COMMIT() asm volatile("cp.async.commit_group;")

// ---------------- fp32 -> bf16 hi/lo split ----------------
__global__ __launch_bounds__(256)
void cvt_split(const float* __restrict__ X, __nv_bfloat16* __restrict__ hi,
               __nv_bfloat16* __restrict__ lo, long nquad, long nquad_src)
{
    long q = (long)blockIdx.x * 256 + threadIdx.x;
    if (q >= nquad) return;
    float4 v = make_float4(0.f, 0.f, 0.f, 0.f);
    if (q < nquad_src) v = *(const float4*)&X[q * 4];
    __nv_bfloat16 h0 = __float2bfloat16(v.x);
    __nv_bfloat16 h1 = __float2bfloat16(v.y);
    __nv_bfloat16 h2 = __float2bfloat16(v.z);
    __nv_bfloat16 h3 = __float2bfloat16(v.w);
    __nv_bfloat16 l0 = __float2bfloat16(v.x - __bfloat162float(h0));
    __nv_bfloat16 l1 = __float2bfloat16(v.y - __bfloat162float(h1));
    __nv_bfloat16 l2 = __float2bfloat16(v.z - __bfloat162float(h2));
    __nv_bfloat16 l3 = __float2bfloat16(v.w - __bfloat162float(h3));
    __nv_bfloat162* hp = (__nv_bfloat162*)&hi[q * 4];
    __nv_bfloat162* lp = (__nv_bfloat162*)&lo[q * 4];
    hp[0] = __nv_bfloat162(h0, h1); hp[1] = __nv_bfloat162(h2, h3);
    lp[0] = __nv_bfloat162(l0, l1); lp[1] = __nv_bfloat162(l2, l3);
}

// ---------------- bf16x3 tensor-core GEMM (R4 config: 128x128, 2-stage) ----------------
#define SM_STRIDE 40
#define STAGE_ELEMS 20480

__global__ __launch_bounds__(256)
void gemm_bf3(const __nv_bfloat16* __restrict__ Ahi, const __nv_bfloat16* __restrict__ Alo,
              const __nv_bfloat16* __restrict__ Bhi, const __nv_bfloat16* __restrict__ Blo,
              float* __restrict__ C, int M, int N, int K, int ldc)
{
    extern __shared__ __nv_bfloat16 sm[];
    const uint32_t sbase = smem_u32(sm);
    const int tid = threadIdx.x;
    const int lane = tid & 31, wid = tid >> 5;
    const int wr = wid & 1, wc = wid >> 1;
    const int row0 = blockIdx.y * 128;
    const int col0 = blockIdx.x * 128;

    float acc[4][4][4];
#pragma unroll
    for (int i = 0; i < 4; i++)
#pragma unroll
        for (int j = 0; j < 4; j++)
#pragma unroll
            for (int k = 0; k < 4; k++) acc[i][j][k] = 0.f;

    const int nt = K >> 5;
    const int ch0 = tid, ch1 = tid + 256;
    const int r0c = ch0 >> 2, s0c = (ch0 & 3) * 8;
    const int r1c = ch1 >> 2, s1c = (ch1 & 3) * 8;

    auto issue = [&](int kt, int stage) {
        uint32_t sb = sbase + stage * (STAGE_ELEMS * 2);
        CPASYNC16(sb + (r0c * SM_STRIDE + s0c) * 2, Ahi + (long)(row0 + r0c) * K + kt + s0c);
        CPASYNC16(sb + (r1c * SM_STRIDE + s1c) * 2, Ahi + (long)(row0 + r1c) * K + kt + s1c);
        CPASYNC16(sb + (5120 + r0c * SM_STRIDE + s0c) * 2, Alo + (long)(row0 + r0c) * K + kt + s0c);
        CPASYNC16(sb + (5120 + r1c * SM_STRIDE + s1c) * 2, Alo + (long)(row0 + r1c) * K + kt + s1c);
        CPASYNC16(sb + (10240 + r0c * SM_STRIDE + s0c) * 2, Bhi + (long)(col0 + r0c) * K + kt + s0c);
        CPASYNC16(sb + (10240 + r1c * SM_STRIDE + s1c) * 2, Bhi + (long)(col0 + r1c) * K + kt + s1c);
        CPASYNC16(sb + (15360 + r0c * SM_STRIDE + s0c) * 2, Blo + (long)(col0 + r0c) * K + kt + s0c);
        CPASYNC16(sb + (15360 + r1c * SM_STRIDE + s1c) * 2, Blo + (long)(col0 + r1c) * K + kt + s1c);
        CP_COMMIT();
    };

    issue(0, 0);

    for (int it = 0; it < nt; it++) {
        if (it + 1 < nt) {
            issue((it + 1) << 5, (it + 1) & 1);
            asm volatile("cp.async.wait_group 1;");
        } else {
            asm volatile("cp.async.wait_group 0;");
        }
        __syncthreads();

        uint32_t sb = sbase + (it & 1) * (STAGE_ELEMS * 2);
#pragma unroll
        for (int kk = 0; kk < 32; kk += 16) {
            uint32_t ah[4][4], al[4][4], bh[4][2], bl[4][2];
#pragma unroll
            for (int mi = 0; mi < 4; mi++) {
                int arow = wr * 64 + mi * 16 + (lane & 15);
                int acol = kk + (lane >> 4) * 8;
                uint32_t ad = sb + (arow * SM_STRIDE + acol) * 2;
                LDMX4(ah[mi][0], ah[mi][1], ah[mi][2], ah[mi][3], ad);
                LDMX4(al[mi][0], al[mi][1], al[mi][2], al[mi][3], ad + 5120 * 2);
            }
#pragma unroll
            for (int half = 0; half < 2; half++) {
                int brow = wc * 32 + half * 16 + (lane & 7) + ((lane >> 4) & 1) * 8;
                int bcol = kk + ((lane >> 3) & 1) * 8;
                uint32_t bd = sb + (10240 + brow * SM_STRIDE + bcol) * 2;
                uint32_t t0, t1, t2, t3;
                LDMX4(t0, t1, t2, t3, bd);
                bh[half*2][0] = t0; bh[half*2][1] = t1;
                bh[half*2+1][0] = t2; bh[half*2+1][1] = t3;
                LDMX4(t0, t1, t2, t3, bd + 5120 * 2);
                bl[half*2][0] = t0; bl[half*2][1] = t1;
                bl[half*2+1][0] = t2; bl[half*2+1][1] = t3;
            }
#pragma unroll
            for (int mi = 0; mi < 4; mi++)
#pragma unroll
                for (int nj = 0; nj < 4; nj++) {
                    MMA16816(acc[mi][nj], ah[mi], bh[nj]);
                    MMA16816(acc[mi][nj], ah[mi], bl[nj]);
                    MMA16816(acc[mi][nj], al[mi], bh[nj]);
                }
        }
        __syncthreads();
    }

#pragma unroll
    for (int mi = 0; mi < 4; mi++) {
        int r = row0 + wr * 64 + mi * 16 + (lane >> 2);
#pragma unroll
        for (int nj = 0; nj < 4; nj++) {
            int cc = col0 + wc * 32 + nj * 8 + (lane & 3) * 2;
            if (cc < N) {
                *(float2*)&C[(long)r * ldc + cc] = make_float2(acc[mi][nj][0], acc[mi][nj][1]);
                *(float2*)&C[(long)(r + 8) * ldc + cc] = make_float2(acc[mi][nj][2], acc[mi][nj][3]);
            }
        }
    }
}

// ---------------- conv1d + silu, emits fp32 + bf16 ----------------
__global__ __launch_bounds__(256)
void conv_silu_kernel(const float* __restrict__ conv_w, const float* __restrict__ conv_b)
{
    __shared__ float t[35][256];
    int tid = threadIdx.x;
    int col = blockIdx.x * 256 + tid;
    int rowstart = blockIdx.y * 32;
    int l0 = rowstart & (LSEQ - 1);

#pragma unroll
    for (int r = 0; r < 35; r++) {
        int l = l0 - 3 + r;
        float v = 0.f;
        if (l >= 0) v = g_zx[(long)(rowstart - 3 + r) * DIP + XBCOFF + col];
        t[r][tid] = v;
    }
    __syncthreads();

    float w0 = conv_w[col * 4 + 0], w1 = conv_w[col * 4 + 1];
    float w2 = conv_w[col * 4 + 2], w3 = conv_w[col * 4 + 3];
    float bb = conv_b[col];
#pragma unroll
    for (int r = 0; r < 32; r++) {
        float acc = bb + t[r][tid] * w0 + t[r + 1][tid] * w1
                       + t[r + 2][tid] * w2 + t[r + 3][tid] * w3;
        float s = acc / (1.f + __expf(-acc));
        g_xc[(long)(rowstart + r) * CONVD + col] = s;
        g_xcb[(long)(rowstart + r) * CONVD + col] = __float2bfloat16(s);
    }
}

// ---------------- dt softplus + per-chunk cumsum ----------------
__global__ __launch_bounds__(256)
void dtcum_kernel(const float* __restrict__ dt_bias, const float* __restrict__ A_log)
{
    __shared__ float sdt[CH][33];
    __shared__ float scum[CH][33];
    int bc = blockIdx.x;
    int b = bc / NC, c = bc % NC;
    int tid = threadIdx.x;
    int rowbase = b * LSEQ + c * CH;

    for (int i = tid; i < CH * NH; i += 256) {
        int l = i >> 5, h = i & 31;
        float raw = g_zx[(long)(rowbase + l) * DIP + DTOFF + h] + dt_bias[h];
        float dtv = (raw > 20.f) ? raw : log1pf(expf(raw));
        sdt[l][h] = dtv;
    }
    __syncthreads();

    if (tid < NH) {
        float Ah = -expf(A_log[tid]);
        float cum = 0.f;
#pragma unroll
        for (int l = 0; l < CH; l++) {
            cum += sdt[l][tid] * Ah;
            scum[l][tid] = cum;
        }
        g_cdecay[bc * NH + tid] = expf(cum);
    }
    __syncthreads();

    for (int i = tid; i < CH * NH; i += 256) {
        int h = i >> 7, l = i & 127;
        g_dtT[(bc * NH + h) * CH + l] = sdt[l][h];
        g_cumT[(bc * NH + h) * CH + l] = scum[l][h];
    }
}

// ---------------- CB = C @ B^T per chunk (bf16 mma) ----------------
__global__ __launch_bounds__(256)
void cb_mma()
{
    extern __shared__ __nv_bfloat16 smc[];
    uint32_t cb = smem_u32(smc);
    uint32_t bb = cb + 17408 * 2;
    int bc = blockIdx.x;
    int b = bc / NC, c = bc % NC;
    int rowbase = b * LSEQ + c * CH;
    int tid = threadIdx.x;
    int lane = tid & 31, wid = tid >> 5;
    int wr = wid & 3, wc = wid >> 2;

    const __nv_bfloat16* Cg = g_xcb + (long)rowbase * CONVD + COFF;
    const __nv_bfloat16* Bg = g_xcb + (long)rowbase * CONVD + BOFF;
#pragma unroll
    for (int k = 0; k < 8; k++) {
        int id = tid + k * 256;
        int s = id >> 4, c8 = (id & 15) * 8;
        CPASYNC16(cb + (s * 136 + c8) * 2, Cg + (long)s * CONVD + c8);
        CPASYNC16(bb + (s * 136 + c8) * 2, Bg + (long)s * CONVD + c8);
    }
    CP_COMMIT();
    asm volatile("cp.async.wait_group 0;");
    __syncthreads();

    float acc[2][8][4];
#pragma unroll
    for (int i = 0; i < 2; i++)
#pragma unroll
        for (int j = 0; j < 8; j++)
#pragma unroll
            for (int k = 0; k < 4; k++) acc[i][j][k] = 0.f;

#pragma unroll
    for (int kk = 0; kk < 128; kk += 16) {
        uint32_t a[2][4];
#pragma unroll
        for (int mi = 0; mi < 2; mi++) {
            int arow = wr * 32 + mi * 16 + (lane & 15);
            int acol = kk + (lane >> 4) * 8;
            LDMX4(a[mi][0], a[mi][1], a[mi][2], a[mi][3], cb + (arow * 136 + acol) * 2);
        }
#pragma unroll
        for (int nb = 0; nb < 4; nb++) {
            int brow = wc * 64 + nb * 16 + (lane & 7) + ((lane >> 4) & 1) * 8;
            int bcol = kk + ((lane >> 3) & 1) * 8;
            uint32_t t0, t1, t2, t3;
            LDMX4(t0, t1, t2, t3, bb + (brow * 136 + bcol) * 2);
            uint32_t b0[2] = {t0, t1}, b1[2] = {t2, t3};
#pragma unroll
            for (int mi = 0; mi < 2; mi++) {
                MMA16816(acc[mi][nb * 2], a[mi], b0);
                MMA16816(acc[mi][nb * 2 + 1], a[mi], b1);
            }
        }
    }

    float* CBo = g_CB + (long)bc * CH * CH;
#pragma unroll
    for (int mi = 0; mi < 2; mi++) {
        int r = wr * 32 + mi * 16 + (lane >> 2);
#pragma unroll
        for (int nj = 0; nj < 8; nj++) {
            int cc = wc * 64 + nj * 8 + (lane & 3) * 2;
            *(float2*)&CBo[r * CH + cc] = make_float2(acc[mi][nj][0], acc[mi][nj][1]);
            *(float2*)&CBo[(r + 8) * CH + cc] = make_float2(acc[mi][nj][2], acc[mi][nj][3]);
        }
    }
}

// ---------------- per-chunk end states (bf16 mma) ----------------
__global__ __launch_bounds__(128)
void states_mma()
{
    extern __shared__ __nv_bfloat16 sms[];
    uint32_t wbase = smem_u32(sms);            // wsx [128][72]
    uint32_t bbase = wbase + 9216 * 2;         // Bb  [128][136]
    __shared__ float ws[CH];

    int bch = blockIdx.x;
    int h = bch % NH;
    int bc = bch / NH;
    int b = bc / NC, c = bc % NC;
    int rowbase = b * LSEQ + c * CH;
    int base = bch * CH;
    int tid = threadIdx.x;
    int lane = tid & 31, wid = tid >> 5;
    int wr = wid & 1, wc = wid >> 1;

    {
        float clast = g_cumT[base + CH - 1];
        ws[tid] = g_dtT[base + tid] * __expf(clast - g_cumT[base + tid]);
    }

    const __nv_bfloat16* Bg = g_xcb + (long)rowbase * CONVD + BOFF;
#pragma unroll
    for (int k = 0; k < 16; k++) {
        int id = tid + k * 128;
        int s = id >> 4, c8 = (id & 15) * 8;
        CPASYNC16(bbase + (s * 136 + c8) * 2, Bg + (long)s * CONVD + c8);
    }
    CP_COMMIT();

    {   // stage ws-scaled x as bf16 [s][p]
        int s = tid;
        float w = ws[s];
        const float* xr = &g_xc[(long)(rowbase + s) * CONVD + XOFF + h * DH];
        __nv_bfloat16* dst = sms + s * 72;
#pragma unroll
        for (int p = 0; p < DH; p += 4) {
            float4 v = *(const float4*)&xr[p];
            __nv_bfloat162* d = (__nv_bfloat162*)&dst[p];
            d[0] = __nv_bfloat162(__float2bfloat16(v.x * w), __float2bfloat16(v.y * w));
            d[1] = __nv_bfloat162(__float2bfloat16(v.z * w), __float2bfloat16(v.w * w));
        }
    }
    asm volatile("cp.async.wait_group 0;");
    __syncthreads();

    float acc[2][8][4];
#pragma unroll
    for (int i = 0; i < 2; i++)
#pragma unroll
        for (int j = 0; j < 8; j++)
#pragma unroll
            for (int k = 0; k < 4; k++) acc[i][j][k] = 0.f;

#pragma unroll
    for (int kk = 0; kk < 128; kk += 16) {
        uint32_t a[2][4];
#pragma unroll
        for (int mi = 0; mi < 2; mi++) {
            int mbase = wr * 32 + mi * 16;
            int srow = kk + (lane & 7) + ((lane >> 4) & 1) * 8;
            int scol = mbase + ((lane >> 3) & 1) * 8;
            LDMX4T(a[mi][0], a[mi][1], a[mi][2], a[mi][3], wbase + (srow * 72 + scol) * 2);
        }
#pragma unroll
        for (int nb = 0; nb < 4; nb++) {
            int nbase = wc * 64 + nb * 16;
            int srow = kk + (lane & 7) + ((lane >> 3) & 1) * 8;
            int scol = nbase + ((lane >> 4) & 1) * 8;
            uint32_t t0, t1, t2, t3;
            LDMX4T(t0, t1, t2, t3, bbase + (srow * 136 + scol) * 2);
            uint32_t b0[2] = {t0, t1}, b1[2] = {t2, t3};
#pragma unroll
            for (int mi = 0; mi < 2; mi++) {
                MMA16816(acc[mi][nb * 2], a[mi], b0);
                MMA16816(acc[mi][nb * 2 + 1], a[mi], b1);
            }
        }
    }

    float* Sp = g_S + (long)bch * DH * DS;
#pragma unroll
    for (int mi = 0; mi < 2; mi++) {
        int r = wr * 32 + mi * 16 + (lane >> 2);
#pragma unroll
        for (int nj = 0; nj < 8; nj++) {
            int cc = wc * 64 + nj * 8 + (lane & 3) * 2;
            *(float2*)&Sp[r * DS + cc] = make_float2(acc[mi][nj][0], acc[mi][nj][1]);
            *(float2*)&Sp[(r + 8) * DS + cc] = make_float2(acc[mi][nj][2], acc[mi][nj][3]);
        }
    }
}

// ---------------- inter-chunk recurrence ----------------
__global__ __launch_bounds__(256)
void scan_kernel()
{
    int bh = blockIdx.x >> 3;
    int slice = blockIdx.x & 7;
    int b = bh >> 5, h = bh & 31;
    int off = slice * 1024 + threadIdx.x * 4;
    float4 carry = make_float4(0.f, 0.f, 0.f, 0.f);
    for (int c = 0; c < NC; c++) {
        int bch = (b * NC + c) * NH + h;
        float d = g_cdecay[bch];
        long idx = (long)bch * (DH * DS) + off;
        float4 s = *(const float4*)&g_S[idx];
        *(float4*)&g_prev[idx] = carry;
        carry.x = carry.x * d + s.x;
        carry.y = carry.y * d + s.y;
        carry.z = carry.z * d + s.z;
        carry.w = carry.w * d + s.w;
    }
}

// ---------------- Y = intra + inter + D*x (bf16 mma) ----------------
__global__ __launch_bounds__(128)
void y_mma(const float* __restrict__ Dparam)
{
    extern __shared__ __nv_bfloat16 smy[];
    uint32_t xb = smem_u32(smy);               // phase1: xb [128][72] (elems 0..9215)
    uint32_t ms = xb + 9216 * 2;               // phase1: Ms [128][24] (elems 9216..12287)
    uint32_t ec = xb;                          // phase2: ElC [128][136]
    uint32_t pb = xb + 17408 * 2;              // phase2: prevb [64][136]
    __shared__ float cl[CH], dts[CH], Fg[CH], El[CH];

    int bch = blockIdx.x;
    int h = bch % NH;
    int bc = bch / NH;
    int b = bc / NC, c = bc % NC;
    int rowbase = b * LSEQ + c * CH;
    int base = bch * CH;
    int tid = threadIdx.x;
    int lane = tid & 31, wid = tid >> 5;

    {
        float cv = g_cumT[base + tid];
        cl[tid] = cv;
        dts[tid] = g_dtT[base + tid];
        El[tid] = __expf(cv);
    }
    const __nv_bfloat16* xg = g_xcb + (long)rowbase * CONVD + XOFF + h * DH;
#pragma unroll
    for (int k = 0; k < 8; k++) {
        int id = tid + k * 128;
        int s = id >> 3, c8 = (id & 7) * 8;
        CPASYNC16(xb + (s * 72 + c8) * 2, xg + (long)s * CONVD + c8);
    }
    CP_COMMIT();
    __syncthreads();                 // cl visible
    Fg[tid] = __expf(cl[tid] - cl[tid & ~7]);
    asm volatile("cp.async.wait_group 0;");
    __syncthreads();

    float acc[2][8][4];
#pragma unroll
    for (int i = 0; i < 2; i++)
#pragma unroll
        for (int j = 0; j < 8; j++)
#pragma unroll
            for (int k = 0; k < 4; k++) acc[i][j][k] = 0.f;

    const float* CBp = g_CB + (long)bc * CH * CH;

    // ---- phase 1: Y_intra ----
    for (int kt = 0; kt < 128; kt += 16) {
        {   // build masked decay matrix tile Ms[l][s-kt] in bf16 (at elem offset 9216)
            int sg = kt + (tid & 15);
            int l0 = (tid >> 4) * 16;
            float dsg = dts[sg], csg = cl[sg];
            int scc = sg - kt;
#pragma unroll
            for (int g = 0; g < 2; g++) {
                int lb = l0 + g * 8;
                float e0 = __expf(fminf(cl[lb] - csg, 85.f)) * dsg;
#pragma unroll
                for (int i = 0; i < 8; i++) {
                    int lg = lb + i;
                    float v = (sg <= lg) ? CBp[lg * CH + sg] * Fg[lg] * e0 : 0.f;
                    smy[9216 + lg * 24 + scc] = __float2bfloat16(v);
                }
            }
        }
        __syncthreads();
        if (kt <= wid * 32 + 31) {
            uint32_t a[2][4];
#pragma unroll
            for (int mi = 0; mi < 2; mi++) {
                int arow = wid * 32 + mi * 16 + (lane & 15);
                int acol = (lane >> 4) * 8;
                LDMX4(a[mi][0], a[mi][1], a[mi][2], a[mi][3], ms + (arow * 24 + acol) * 2);
            }
#pragma unroll
            for (int nb = 0; nb < 4; nb++) {   // B = x^T via trans ldmatrix
                int nbase = nb * 16;
                int srow = kt + (lane & 7) + ((lane >> 3) & 1) * 8;
                int scol = nbase + ((lane >> 4) & 1) * 8;
                uint32_t t0, t1, t2, t3;
                LDMX4T(t0, t1, t2, t3, xb + (srow * 72 + scol) * 2);
                uint32_t b0[2] = {t0, t1}, b1[2] = {t2, t3};
#pragma unroll
                for (int mi = 0; mi < 2; mi++) {
                    MMA16816(acc[mi][nb * 2], a[mi], b0);
                    MMA16816(acc[mi][nb * 2 + 1], a[mi], b1);
                }
            }
        }
        __syncthreads();
    }

    // ---- phase 2 staging: ElC [128][136], prevb [64][136] ----
    {
        int l = tid;
        float el = El[l];
        const __nv_bfloat16* Cg = g_xcb + (long)(rowbase + l) * CONVD + COFF;
        __nv_bfloat16* dst = smy + l * 136;
#pragma unroll
        for (int n = 0; n < 128; n += 2) {
            __nv_bfloat162 cv = *(const __nv_bfloat162*)&Cg[n];
            *(__nv_bfloat162*)&dst[n] = __nv_bfloat162(
                __float2bfloat16(__bfloat162float(cv.x) * el),
                __float2bfloat16(__bfloat162float(cv.y) * el));
        }
        const float* Pv = g_prev + (long)bch * DH * DS;
        int p = tid >> 1, n0 = (tid & 1) * 64;
        __nv_bfloat16* pdst = smy + 17408 + p * 136;
#pragma unroll
        for (int n = 0; n < 64; n += 4) {
            float4 v = *(const float4*)&Pv[p * DS + n0 + n];
            __nv_bfloat162* d = (__nv_bfloat162*)&pdst[n0 + n];
            d[0] = __nv_bfloat162(__float2bfloat16(v.x), __float2bfloat16(v.y));
            d[1] = __nv_bfloat162(__float2bfloat16(v.z), __float2bfloat16(v.w));
        }
    }
    __syncthreads();

    // ---- phase 2: Y_inter = (El*C) @ prev^T ----
#pragma unroll
    for (int nt = 0; nt < 128; nt += 16) {
        uint32_t a[2][4];
#pragma unroll
        for (int mi = 0; mi < 2; mi++) {
            int arow = wid * 32 + mi * 16 + (lane & 15);
            int acol = nt + (lane >> 4) * 8;
            LDMX4(a[mi][0], a[mi][1], a[mi][2], a[mi][3], ec + (arow * 136 + acol) * 2);
        }
#pragma unroll
        for (int nb = 0; nb < 4; nb++) {
            int brow = nb * 16 + (lane & 7) + ((lane >> 4) & 1) * 8;
            int bcol = nt + ((lane >> 3) & 1) * 8;
            uint32_t t0, t1, t2, t3;
            LDMX4(t0, t1, t2, t3, pb + (brow * 136 + bcol) * 2);
            uint32_t b0[2] = {t0, t1}, b1[2] = {t2, t3};
#pragma unroll
            for (int mi = 0; mi < 2; mi++) {
                MMA16816(acc[mi][nb * 2], a[mi], b0);
                MMA16816(acc[mi][nb * 2 + 1], a[mi], b1);
            }
        }
    }

    // ---- epilogue: + D*x, store fp32 y ----
    float Dh = Dparam[h];
#pragma unroll
    for (int mi = 0; mi < 2; mi++) {
        int r = wid * 32 + mi * 16 + (lane >> 2);
#pragma unroll
        for (int nj = 0; nj < 8; nj++) {
            int cc = nj * 8 + (lane & 3) * 2;
            {
                int row = rowbase + r;
                float2 xv = *(const float2*)&g_xc[(long)row * CONVD + XOFF + h * DH + cc];
                *(float2*)&g_y[(long)row * DSSM + h * DH + cc] =
                    make_float2(acc[mi][nj][0] + Dh * xv.x, acc[mi][nj][1] + Dh * xv.y);
            }
            {
                int row = rowbase + r + 8;
                float2 xv = *(const float2*)&g_xc[(long)row * CONVD + XOFF + h * DH + cc];
                *(float2*)&g_y[(long)row * DSSM + h * DH + cc] =
                    make_float2(acc[mi][nj][2] + Dh * xv.x, acc[mi][nj][3] + Dh * xv.y);
            }
        }
    }
}

// ---------------- gate + RMSNorm, emits bf16 hi/lo ----------------
__global__ __launch_bounds__(256)
void gatenorm_kernel(const float* __restrict__ norm_w)
{
    int row = blockIdx.x;
    int tid = threadIdx.x;
    float v[8];
    float ss = 0.f;
#pragma unroll
    for (int j = 0; j < 8; j++) {
        int cidx = tid + j * 256;
        float y = g_y[(long)row * DSSM + cidx];
        float z = g_zx[(long)row * DIP + ZOFF + cidx];
        float g = z / (1.f + __expf(-z));
        float yg = y * g;
        v[j] = yg;
        ss += yg * yg;
    }
#pragma unroll
    for (int o = 16; o > 0; o >>= 1) ss += __shfl_xor_sync(0xffffffffu, ss, o);
    __shared__ float red[8];
    __shared__ float rinv;
    if ((tid & 31) == 0) red[tid >> 5] = ss;
    __syncthreads();
    if (tid == 0) {
        float t = 0.f;
#pragma unroll
        for (int i = 0; i < 8; i++) t += red[i];
        rinv = rsqrtf(t / (float)DSSM + 1e-5f);
    }
    __syncthreads();
    float r = rinv;
#pragma unroll
    for (int j = 0; j < 8; j++) {
        int cidx = tid + j * 256;
        float val = v[j] * r * norm_w[cidx];
        __nv_bfloat16 hh = __float2bfloat16(val);
        __nv_bfloat16 ll = __float2bfloat16(val - __bfloat162float(hh));
        g_yhi[(long)row * DSSM + cidx] = hh;
        g_ylo[(long)row * DSSM + cidx] = ll;
    }
}

// ---------------- host launcher ----------------
extern "C" void kernel_launch(void* const* d_in, const int* in_sizes, int n_in,
                              void* d_out, int out_size)
{
    const float* u       = (const float*)d_in[0];
    const float* W_in    = (const float*)d_in[1];
    const float* conv_w  = (const float*)d_in[2];
    const float* conv_b  = (const float*)d_in[3];
    const float* dt_bias = (const float*)d_in[4];
    const float* A_log   = (const float*)d_in[5];
    const float* Dp      = (const float*)d_in[6];
    const float* norm_w  = (const float*)d_in[7];
    const float* W_out   = (const float*)d_in[8];
    float* out = (float*)d_out;

    float *p_zx;
    cudaGetSymbolAddress((void**)&p_zx, g_zx);
    __nv_bfloat16 *p_uhi, *p_ulo, *p_w1hi, *p_w1lo, *p_yhi, *p_ylo, *p_w2hi, *p_w2lo;
    cudaGetSymbolAddress((void**)&p_uhi, g_uhi);
    cudaGetSymbolAddress((void**)&p_ulo, g_ulo);
    cudaGetSymbolAddress((void**)&p_w1hi, g_w1hi);
    cudaGetSymbolAddress((void**)&p_w1lo, g_w1lo);
    cudaGetSymbolAddress((void**)&p_yhi, g_yhi);
    cudaGetSymbolAddress((void**)&p_ylo, g_ylo);
    cudaGetSymbolAddress((void**)&p_w2hi, g_w2hi);
    cudaGetSymbolAddress((void**)&p_w2lo, g_w2lo);

    static int smem_set = 0;
    if (!smem_set) {
        cudaFuncSetAttribute(gemm_bf3, cudaFuncAttributeMaxDynamicSharedMemorySize, 2 * STAGE_ELEMS * 2);
        cudaFuncSetAttribute(cb_mma, cudaFuncAttributeMaxDynamicSharedMemorySize, 69632);
        cudaFuncSetAttribute(states_mma, cudaFuncAttributeMaxDynamicSharedMemorySize, 53248);
        cudaFuncSetAttribute(y_mma, cudaFuncAttributeMaxDynamicSharedMemorySize, 52224);
        smem_set = 1;
    }

    // 0) bf16 hi/lo conversions
    {
        long nq = (long)ROWS * DM / 4;
        cvt_split<<<(nq + 255) / 256, 256>>>(u, p_uhi, p_ulo, nq, nq);
    }
    {
        long nq = (long)DIPPAD * DM / 4, ns = (long)DIP * DM / 4;
        cvt_split<<<(nq + 255) / 256, 256>>>(W_in, p_w1hi, p_w1lo, nq, ns);
    }
    {
        long nq = (long)DM * DSSM / 4;
        cvt_split<<<(nq + 255) / 256, 256>>>(W_out, p_w2hi, p_w2lo, nq, nq);
    }

    // 1) in_proj
    gemm_bf3<<<dim3(DIPPAD / 128, ROWS / 128), 256, 2 * STAGE_ELEMS * 2>>>(
        p_uhi, p_ulo, p_w1hi, p_w1lo, p_zx, ROWS, DIP, DM, DIP);

    // 2) conv + silu (fp32 + bf16 out)
    conv_silu_kernel<<<dim3(CONVD / 256, ROWS / 32), 256>>>(conv_w, conv_b);

    // 3) dt / cumsum
    dtcum_kernel<<<BATCH * NC, 256>>>(dt_bias, A_log);

    // 4) CB = C @ B^T (tensor cores)
    cb_mma<<<BATCH * NC, 256, 69632>>>();

    // 5) per-chunk end states (tensor cores)
    states_mma<<<BATCH * NC * NH, 128, 53248>>>();

    // 6) inter-chunk scan
    scan_kernel<<<BATCH * NH * 8, 256>>>();

    // 7) Y (tensor cores)
    y_mma<<<BATCH * NC * NH, 128, 52224>>>(Dp);

    // 8) gate + RMSNorm
    gatenorm_kernel<<<ROWS, 256>>>(norm_w);

    // 9) out_proj
    gemm_bf3<<<dim3(DM / 128, ROWS / 128), 256, 2 * STAGE_ELEMS * 2>>>(
        p_yhi, p_ylo, p_w2hi, p_w2lo, out, ROWS, DM, DSSM, DM);

    (void)in_sizes; (void)n_in; (void)out_size;
}

// round 10
// speedup vs baseline: 1.1162x; 1.0179x over previous
#include <cuda_runtime.h>
#include <cuda_bf16.h>
#include <cstdint>
#include <math.h>

// ---------------- problem constants ----------------
#define BATCH   2
#define LSEQ    2048
#define DM      1024
#define DIP     4384
#define DIPPAD  4480
#define DSSM    2048
#define CONVD   2304
#define NH      32
#define DH      64
#define DS      128
#define CH      128
#define NC      (LSEQ / CH)
#define ROWS    (BATCH * LSEQ)
#define ZOFF    0
#define XBCOFF  2048
#define DTOFF   4352
#define XOFF    0
#define BOFF    2048
#define COFF    2176

// ---------------- scratch ----------------
__device__ float g_zx[ROWS * DIP];
__device__ float g_xc[ROWS * CONVD];
__device__ __nv_bfloat16 g_xcb[ROWS * CONVD];   // bf16 copy of conv output
__device__ float g_dtT[BATCH * NC * NH * CH];
__device__ float g_cumT[BATCH * NC * NH * CH];
__device__ float g_cdecay[BATCH * NC * NH];
__device__ float g_CB[BATCH * NC * CH * CH];
__device__ float g_S[BATCH * NC * NH * DH * DS];
__device__ float g_prev[BATCH * NC * NH * DH * DS];
__device__ float g_y[ROWS * DSSM];

__device__ __nv_bfloat16 g_uhi[ROWS * DM],   g_ulo[ROWS * DM];
__device__ __nv_bfloat16 g_w1hi[DIPPAD * DM], g_w1lo[DIPPAD * DM];
__device__ __nv_bfloat16 g_yhi[ROWS * DSSM], g_ylo[ROWS * DSSM];
__device__ __nv_bfloat16 g_w2hi[DM * DSSM],  g_w2lo[DM * DSSM];

// ---------------- PTX helpers ----------------
__device__ __forceinline__ uint32_t smem_u32(const void* p) {
    return (uint32_t)__cvta_generic_to_shared(p);
}
#define LDMX4(r0,r1,r2,r3,addr) \
    asm volatile("ldmatrix.sync.aligned.m8n8.x4.shared.b16 {%0,%1,%2,%3}, [%4];" \
                 : "=r"(r0),"=r"(r1),"=r"(r2),"=r"(r3) : "r"(addr))
#define LDMX4T(r0,r1,r2,r3,addr) \
    asm volatile("ldmatrix.sync.aligned.m8n8.x4.trans.shared.b16 {%0,%1,%2,%3}, [%4];" \
                 : "=r"(r0),"=r"(r1),"=r"(r2),"=r"(r3) : "r"(addr))
#define MMA16816(d,a,b) \
    asm volatile("mma.sync.aligned.m16n8k16.row.col.f32.bf16.bf16.f32 " \
                 "{%0,%1,%2,%3},{%4,%5,%6,%7},{%8,%9},{%0,%1,%2,%3};" \
                 : "+f"((d)[0]),"+f"((d)[1]),"+f"((d)[2]),"+f"((d)[3]) \
                 : "r"((a)[0]),"r"((a)[1]),"r"((a)[2]),"r"((a)[3]),"r"((b)[0]),"r"((b)[1]))
#define CPASYNC16(s,g) \
    asm volatile("cp.async.cg.shared.global [%0], [%1], 16;" :: "r"(s),"l"(g))
#define CP_COMMIT() asm volatile("cp.async.commit_group;")

// ---------------- fp32 -> bf16 hi/lo split ----------------
__global__ __launch_bounds__(256)
void cvt_split(const float* __restrict__ X, __nv_bfloat16* __restrict__ hi,
               __nv_bfloat16* __restrict__ lo, long nquad, long nquad_src)
{
    long q = (long)blockIdx.x * 256 + threadIdx.x;
    if (q >= nquad) return;
    float4 v = make_float4(0.f, 0.f, 0.f, 0.f);
    if (q < nquad_src) v = *(const float4*)&X[q * 4];
    __nv_bfloat16 h0 = __float2bfloat16(v.x);
    __nv_bfloat16 h1 = __float2bfloat16(v.y);
    __nv_bfloat16 h2 = __float2bfloat16(v.z);
    __nv_bfloat16 h3 = __float2bfloat16(v.w);
    __nv_bfloat16 l0 = __float2bfloat16(v.x - __bfloat162float(h0));
    __nv_bfloat16 l1 = __float2bfloat16(v.y - __bfloat162float(h1));
    __nv_bfloat16 l2 = __float2bfloat16(v.z - __bfloat162float(h2));
    __nv_bfloat16 l3 = __float2bfloat16(v.w - __bfloat162float(h3));
    __nv_bfloat162* hp = (__nv_bfloat162*)&hi[q * 4];
    __nv_bfloat162* lp = (__nv_bfloat162*)&lo[q * 4];
    hp[0] = __nv_bfloat162(h0, h1); hp[1] = __nv_bfloat162(h2, h3);
    lp[0] = __nv_bfloat162(l0, l1); lp[1] = __nv_bfloat162(l2, l3);
}

// ---------------- bf16x3 tensor-core GEMM (128x128, 2-stage, 1 barrier/iter) ----------------
#define SM_STRIDE 40
#define STAGE_ELEMS 20480

__global__ __launch_bounds__(256)
void gemm_bf3(const __nv_bfloat16* __restrict__ Ahi, const __nv_bfloat16* __restrict__ Alo,
              const __nv_bfloat16* __restrict__ Bhi, const __nv_bfloat16* __restrict__ Blo,
              float* __restrict__ C, int M, int N, int K, int ldc)
{
    extern __shared__ __nv_bfloat16 sm[];
    const uint32_t sbase = smem_u32(sm);
    const int tid = threadIdx.x;
    const int lane = tid & 31, wid = tid >> 5;
    const int wr = wid & 1, wc = wid >> 1;
    const int row0 = blockIdx.y * 128;
    const int col0 = blockIdx.x * 128;

    float acc[4][4][4];
#pragma unroll
    for (int i = 0; i < 4; i++)
#pragma unroll
        for (int j = 0; j < 4; j++)
#pragma unroll
            for (int k = 0; k < 4; k++) acc[i][j][k] = 0.f;

    const int nt = K >> 5;
    const int ch0 = tid, ch1 = tid + 256;
    const int r0c = ch0 >> 2, s0c = (ch0 & 3) * 8;
    const int r1c = ch1 >> 2, s1c = (ch1 & 3) * 8;

    auto issue = [&](int kt, int stage) {
        uint32_t sb = sbase + stage * (STAGE_ELEMS * 2);
        CPASYNC16(sb + (r0c * SM_STRIDE + s0c) * 2, Ahi + (long)(row0 + r0c) * K + kt + s0c);
        CPASYNC16(sb + (r1c * SM_STRIDE + s1c) * 2, Ahi + (long)(row0 + r1c) * K + kt + s1c);
        CPASYNC16(sb + (5120 + r0c * SM_STRIDE + s0c) * 2, Alo + (long)(row0 + r0c) * K + kt + s0c);
        CPASYNC16(sb + (5120 + r1c * SM_STRIDE + s1c) * 2, Alo + (long)(row0 + r1c) * K + kt + s1c);
        CPASYNC16(sb + (10240 + r0c * SM_STRIDE + s0c) * 2, Bhi + (long)(col0 + r0c) * K + kt + s0c);
        CPASYNC16(sb + (10240 + r1c * SM_STRIDE + s1c) * 2, Bhi + (long)(col0 + r1c) * K + kt + s1c);
        CPASYNC16(sb + (15360 + r0c * SM_STRIDE + s0c) * 2, Blo + (long)(col0 + r0c) * K + kt + s0c);
        CPASYNC16(sb + (15360 + r1c * SM_STRIDE + s1c) * 2, Blo + (long)(col0 + r1c) * K + kt + s1c);
        CP_COMMIT();
    };

    issue(0, 0);

    for (int it = 0; it < nt; it++) {
        // stage `it` was issued one iteration ago -> has had a full compute iteration to land
        asm volatile("cp.async.wait_group 0;");
        __syncthreads();   // (a) makes stage `it` visible; (b) separates prior compute reads
                           //     of stage (it+1)&1 from the cp.async writes issued next
        if (it + 1 < nt) issue((it + 1) << 5, (it + 1) & 1);

        uint32_t sb = sbase + (it & 1) * (STAGE_ELEMS * 2);
#pragma unroll
        for (int kk = 0; kk < 32; kk += 16) {
            uint32_t ah[4][4], al[4][4], bh[4][2], bl[4][2];
#pragma unroll
            for (int mi = 0; mi < 4; mi++) {
                int arow = wr * 64 + mi * 16 + (lane & 15);
                int acol = kk + (lane >> 4) * 8;
                uint32_t ad = sb + (arow * SM_STRIDE + acol) * 2;
                LDMX4(ah[mi][0], ah[mi][1], ah[mi][2], ah[mi][3], ad);
                LDMX4(al[mi][0], al[mi][1], al[mi][2], al[mi][3], ad + 5120 * 2);
            }
#pragma unroll
            for (int half = 0; half < 2; half++) {
                int brow = wc * 32 + half * 16 + (lane & 7) + ((lane >> 4) & 1) * 8;
                int bcol = kk + ((lane >> 3) & 1) * 8;
                uint32_t bd = sb + (10240 + brow * SM_STRIDE + bcol) * 2;
                uint32_t t0, t1, t2, t3;
                LDMX4(t0, t1, t2, t3, bd);
                bh[half*2][0] = t0; bh[half*2][1] = t1;
                bh[half*2+1][0] = t2; bh[half*2+1][1] = t3;
                LDMX4(t0, t1, t2, t3, bd + 5120 * 2);
                bl[half*2][0] = t0; bl[half*2][1] = t1;
                bl[half*2+1][0] = t2; bl[half*2+1][1] = t3;
            }
#pragma unroll
            for (int mi = 0; mi < 4; mi++)
#pragma unroll
                for (int nj = 0; nj < 4; nj++) {
                    MMA16816(acc[mi][nj], ah[mi], bh[nj]);
                    MMA16816(acc[mi][nj], ah[mi], bl[nj]);
                    MMA16816(acc[mi][nj], al[mi], bh[nj]);
                }
        }
    }

#pragma unroll
    for (int mi = 0; mi < 4; mi++) {
        int r = row0 + wr * 64 + mi * 16 + (lane >> 2);
#pragma unroll
        for (int nj = 0; nj < 4; nj++) {
            int cc = col0 + wc * 32 + nj * 8 + (lane & 3) * 2;
            if (cc < N) {
                *(float2*)&C[(long)r * ldc + cc] = make_float2(acc[mi][nj][0], acc[mi][nj][1]);
                *(float2*)&C[(long)(r + 8) * ldc + cc] = make_float2(acc[mi][nj][2], acc[mi][nj][3]);
            }
        }
    }
}

// ---------------- conv1d + silu, emits fp32 + bf16 ----------------
__global__ __launch_bounds__(256)
void conv_silu_kernel(const float* __restrict__ conv_w, const float* __restrict__ conv_b)
{
    __shared__ float t[35][256];
    int tid = threadIdx.x;
    int col = blockIdx.x * 256 + tid;
    int rowstart = blockIdx.y * 32;
    int l0 = rowstart & (LSEQ - 1);

#pragma unroll
    for (int r = 0; r < 35; r++) {
        int l = l0 - 3 + r;
        float v = 0.f;
        if (l >= 0) v = g_zx[(long)(rowstart - 3 + r) * DIP + XBCOFF + col];
        t[r][tid] = v;
    }
    __syncthreads();

    float w0 = conv_w[col * 4 + 0], w1 = conv_w[col * 4 + 1];
    float w2 = conv_w[col * 4 + 2], w3 = conv_w[col * 4 + 3];
    float bb = conv_b[col];
#pragma unroll
    for (int r = 0; r < 32; r++) {
        float acc = bb + t[r][tid] * w0 + t[r + 1][tid] * w1
                       + t[r + 2][tid] * w2 + t[r + 3][tid] * w3;
        float s = acc / (1.f + __expf(-acc));
        g_xc[(long)(rowstart + r) * CONVD + col] = s;
        g_xcb[(long)(rowstart + r) * CONVD + col] = __float2bfloat16(s);
    }
}

// ---------------- dt softplus + per-chunk cumsum ----------------
__global__ __launch_bounds__(256)
void dtcum_kernel(const float* __restrict__ dt_bias, const float* __restrict__ A_log)
{
    __shared__ float sdt[CH][33];
    __shared__ float scum[CH][33];
    int bc = blockIdx.x;
    int b = bc / NC, c = bc % NC;
    int tid = threadIdx.x;
    int rowbase = b * LSEQ + c * CH;

    for (int i = tid; i < CH * NH; i += 256) {
        int l = i >> 5, h = i & 31;
        float raw = g_zx[(long)(rowbase + l) * DIP + DTOFF + h] + dt_bias[h];
        float dtv = (raw > 20.f) ? raw : log1pf(expf(raw));
        sdt[l][h] = dtv;
    }
    __syncthreads();

    if (tid < NH) {
        float Ah = -expf(A_log[tid]);
        float cum = 0.f;
#pragma unroll
        for (int l = 0; l < CH; l++) {
            cum += sdt[l][tid] * Ah;
            scum[l][tid] = cum;
        }
        g_cdecay[bc * NH + tid] = expf(cum);
    }
    __syncthreads();

    for (int i = tid; i < CH * NH; i += 256) {
        int h = i >> 7, l = i & 127;
        g_dtT[(bc * NH + h) * CH + l] = sdt[l][h];
        g_cumT[(bc * NH + h) * CH + l] = scum[l][h];
    }
}

// ---------------- CB = C @ B^T per chunk (bf16 mma) ----------------
__global__ __launch_bounds__(256)
void cb_mma()
{
    extern __shared__ __nv_bfloat16 smc[];
    uint32_t cb = smem_u32(smc);
    uint32_t bb = cb + 17408 * 2;
    int bc = blockIdx.x;
    int b = bc / NC, c = bc % NC;
    int rowbase = b * LSEQ + c * CH;
    int tid = threadIdx.x;
    int lane = tid & 31, wid = tid >> 5;
    int wr = wid & 3, wc = wid >> 2;

    const __nv_bfloat16* Cg = g_xcb + (long)rowbase * CONVD + COFF;
    const __nv_bfloat16* Bg = g_xcb + (long)rowbase * CONVD + BOFF;
#pragma unroll
    for (int k = 0; k < 8; k++) {
        int id = tid + k * 256;
        int s = id >> 4, c8 = (id & 15) * 8;
        CPASYNC16(cb + (s * 136 + c8) * 2, Cg + (long)s * CONVD + c8);
        CPASYNC16(bb + (s * 136 + c8) * 2, Bg + (long)s * CONVD + c8);
    }
    CP_COMMIT();
    asm volatile("cp.async.wait_group 0;");
    __syncthreads();

    float acc[2][8][4];
#pragma unroll
    for (int i = 0; i < 2; i++)
#pragma unroll
        for (int j = 0; j < 8; j++)
#pragma unroll
            for (int k = 0; k < 4; k++) acc[i][j][k] = 0.f;

#pragma unroll
    for (int kk = 0; kk < 128; kk += 16) {
        uint32_t a[2][4];
#pragma unroll
        for (int mi = 0; mi < 2; mi++) {
            int arow = wr * 32 + mi * 16 + (lane & 15);
            int acol = kk + (lane >> 4) * 8;
            LDMX4(a[mi][0], a[mi][1], a[mi][2], a[mi][3], cb + (arow * 136 + acol) * 2);
        }
#pragma unroll
        for (int nb = 0; nb < 4; nb++) {
            int brow = wc * 64 + nb * 16 + (lane & 7) + ((lane >> 4) & 1) * 8;
            int bcol = kk + ((lane >> 3) & 1) * 8;
            uint32_t t0, t1, t2, t3;
            LDMX4(t0, t1, t2, t3, bb + (brow * 136 + bcol) * 2);
            uint32_t b0[2] = {t0, t1}, b1[2] = {t2, t3};
#pragma unroll
            for (int mi = 0; mi < 2; mi++) {
                MMA16816(acc[mi][nb * 2], a[mi], b0);
                MMA16816(acc[mi][nb * 2 + 1], a[mi], b1);
            }
        }
    }

    float* CBo = g_CB + (long)bc * CH * CH;
#pragma unroll
    for (int mi = 0; mi < 2; mi++) {
        int r = wr * 32 + mi * 16 + (lane >> 2);
#pragma unroll
        for (int nj = 0; nj < 8; nj++) {
            int cc = wc * 64 + nj * 8 + (lane & 3) * 2;
            *(float2*)&CBo[r * CH + cc] = make_float2(acc[mi][nj][0], acc[mi][nj][1]);
            *(float2*)&CBo[(r + 8) * CH + cc] = make_float2(acc[mi][nj][2], acc[mi][nj][3]);
        }
    }
}

// ---------------- per-chunk end states (bf16 mma) ----------------
__global__ __launch_bounds__(128)
void states_mma()
{
    extern __shared__ __nv_bfloat16 sms[];
    uint32_t wbase = smem_u32(sms);            // wsx [128][72]
    uint32_t bbase = wbase + 9216 * 2;         // Bb  [128][136]
    __shared__ float ws[CH];

    int bch = blockIdx.x;
    int h = bch % NH;
    int bc = bch / NH;
    int b = bc / NC, c = bc % NC;
    int rowbase = b * LSEQ + c * CH;
    int base = bch * CH;
    int tid = threadIdx.x;
    int lane = tid & 31, wid = tid >> 5;
    int wr = wid & 1, wc = wid >> 1;

    {
        float clast = g_cumT[base + CH - 1];
        ws[tid] = g_dtT[base + tid] * __expf(clast - g_cumT[base + tid]);
    }

    const __nv_bfloat16* Bg = g_xcb + (long)rowbase * CONVD + BOFF;
#pragma unroll
    for (int k = 0; k < 16; k++) {
        int id = tid + k * 128;
        int s = id >> 4, c8 = (id & 15) * 8;
        CPASYNC16(bbase + (s * 136 + c8) * 2, Bg + (long)s * CONVD + c8);
    }
    CP_COMMIT();

    {
        int s = tid;
        float w = ws[s];
        const float* xr = &g_xc[(long)(rowbase + s) * CONVD + XOFF + h * DH];
        __nv_bfloat16* dst = sms + s * 72;
#pragma unroll
        for (int p = 0; p < DH; p += 4) {
            float4 v = *(const float4*)&xr[p];
            __nv_bfloat162* d = (__nv_bfloat162*)&dst[p];
            d[0] = __nv_bfloat162(__float2bfloat16(v.x * w), __float2bfloat16(v.y * w));
            d[1] = __nv_bfloat162(__float2bfloat16(v.z * w), __float2bfloat16(v.w * w));
        }
    }
    asm volatile("cp.async.wait_group 0;");
    __syncthreads();

    float acc[2][8][4];
#pragma unroll
    for (int i = 0; i < 2; i++)
#pragma unroll
        for (int j = 0; j < 8; j++)
#pragma unroll
            for (int k = 0; k < 4; k++) acc[i][j][k] = 0.f;

#pragma unroll
    for (int kk = 0; kk < 128; kk += 16) {
        uint32_t a[2][4];
#pragma unroll
        for (int mi = 0; mi < 2; mi++) {
            int mbase = wr * 32 + mi * 16;
            int srow = kk + (lane & 7) + ((lane >> 4) & 1) * 8;
            int scol = mbase + ((lane >> 3) & 1) * 8;
            LDMX4T(a[mi][0], a[mi][1], a[mi][2], a[mi][3], wbase + (srow * 72 + scol) * 2);
        }
#pragma unroll
        for (int nb = 0; nb < 4; nb++) {
            int nbase = wc * 64 + nb * 16;
            int srow = kk + (lane & 7) + ((lane >> 3) & 1) * 8;
            int scol = nbase + ((lane >> 4) & 1) * 8;
            uint32_t t0, t1, t2, t3;
            LDMX4T(t0, t1, t2, t3, bbase + (srow * 136 + scol) * 2);
            uint32_t b0[2] = {t0, t1}, b1[2] = {t2, t3};
#pragma unroll
            for (int mi = 0; mi < 2; mi++) {
                MMA16816(acc[mi][nb * 2], a[mi], b0);
                MMA16816(acc[mi][nb * 2 + 1], a[mi], b1);
            }
        }
    }

    float* Sp = g_S + (long)bch * DH * DS;
#pragma unroll
    for (int mi = 0; mi < 2; mi++) {
        int r = wr * 32 + mi * 16 + (lane >> 2);
#pragma unroll
        for (int nj = 0; nj < 8; nj++) {
            int cc = wc * 64 + nj * 8 + (lane & 3) * 2;
            *(float2*)&Sp[r * DS + cc] = make_float2(acc[mi][nj][0], acc[mi][nj][1]);
            *(float2*)&Sp[(r + 8) * DS + cc] = make_float2(acc[mi][nj][2], acc[mi][nj][3]);
        }
    }
}

// ---------------- inter-chunk recurrence ----------------
__global__ __launch_bounds__(256)
void scan_kernel()
{
    int bh = blockIdx.x >> 3;
    int slice = blockIdx.x & 7;
    int b = bh >> 5, h = bh & 31;
    int off = slice * 1024 + threadIdx.x * 4;
    float4 carry = make_float4(0.f, 0.f, 0.f, 0.f);
    for (int c = 0; c < NC; c++) {
        int bch = (b * NC + c) * NH + h;
        float d = g_cdecay[bch];
        long idx = (long)bch * (DH * DS) + off;
        float4 s = *(const float4*)&g_S[idx];
        *(float4*)&g_prev[idx] = carry;
        carry.x = carry.x * d + s.x;
        carry.y = carry.y * d + s.y;
        carry.z = carry.z * d + s.z;
        carry.w = carry.w * d + s.w;
    }
}

// ---------------- Y = intra + inter + D*x (bf16 mma) ----------------
__global__ __launch_bounds__(128)
void y_mma(const float* __restrict__ Dparam)
{
    extern __shared__ __nv_bfloat16 smy[];
    uint32_t xb = smem_u32(smy);               // phase1: xb [128][72]
    uint32_t ms = xb + 9216 * 2;               // phase1: Ms [128][24]
    uint32_t ec = xb;                          // phase2: ElC [128][136]
    uint32_t pb = xb + 17408 * 2;              // phase2: prevb [64][136]
    __shared__ float cl[CH], dts[CH], Fg[CH], El[CH];

    int bch = blockIdx.x;
    int h = bch % NH;
    int bc = bch / NH;
    int b = bc / NC, c = bc % NC;
    int rowbase = b * LSEQ + c * CH;
    int base = bch * CH;
    int tid = threadIdx.x;
    int lane = tid & 31, wid = tid >> 5;

    {
        float cv = g_cumT[base + tid];
        cl[tid] = cv;
        dts[tid] = g_dtT[base + tid];
        El[tid] = __expf(cv);
    }
    const __nv_bfloat16* xg = g_xcb + (long)rowbase * CONVD + XOFF + h * DH;
#pragma unroll
    for (int k = 0; k < 8; k++) {
        int id = tid + k * 128;
        int s = id >> 3, c8 = (id & 7) * 8;
        CPASYNC16(xb + (s * 72 + c8) * 2, xg + (long)s * CONVD + c8);
    }
    CP_COMMIT();
    __syncthreads();
    Fg[tid] = __expf(cl[tid] - cl[tid & ~7]);
    asm volatile("cp.async.wait_group 0;");
    __syncthreads();

    float acc[2][8][4];
#pragma unroll
    for (int i = 0; i < 2; i++)
#pragma unroll
        for (int j = 0; j < 8; j++)
#pragma unroll
            for (int k = 0; k < 4; k++) acc[i][j][k] = 0.f;

    const float* CBp = g_CB + (long)bc * CH * CH;

    // ---- phase 1: Y_intra ----
    for (int kt = 0; kt < 128; kt += 16) {
        {
            int sg = kt + (tid & 15);
            int l0 = (tid >> 4) * 16;
            float dsg = dts[sg], csg = cl[sg];
            int scc = sg - kt;
#pragma unroll
            for (int g = 0; g < 2; g++) {
                int lb = l0 + g * 8;
                float e0 = __expf(fminf(cl[lb] - csg, 85.f)) * dsg;
#pragma unroll
                for (int i = 0; i < 8; i++) {
                    int lg = lb + i;
                    float v = (sg <= lg) ? CBp[lg * CH + sg] * Fg[lg] * e0 : 0.f;
                    smy[9216 + lg * 24 + scc] = __float2bfloat16(v);
                }
            }
        }
        __syncthreads();
        if (kt <= wid * 32 + 31) {
            uint32_t a[2][4];
#pragma unroll
            for (int mi = 0; mi < 2; mi++) {
                int arow = wid * 32 + mi * 16 + (lane & 15);
                int acol = (lane >> 4) * 8;
                LDMX4(a[mi][0], a[mi][1], a[mi][2], a[mi][3], ms + (arow * 24 + acol) * 2);
            }
#pragma unroll
            for (int nb = 0; nb < 4; nb++) {
                int nbase = nb * 16;
                int srow = kt + (lane & 7) + ((lane >> 3) & 1) * 8;
                int scol = nbase + ((lane >> 4) & 1) * 8;
                uint32_t t0, t1, t2, t3;
                LDMX4T(t0, t1, t2, t3, xb + (srow * 72 + scol) * 2);
                uint32_t b0[2] = {t0, t1}, b1[2] = {t2, t3};
#pragma unroll
                for (int mi = 0; mi < 2; mi++) {
                    MMA16816(acc[mi][nb * 2], a[mi], b0);
                    MMA16816(acc[mi][nb * 2 + 1], a[mi], b1);
                }
            }
        }
        __syncthreads();
    }

    // ---- phase 2 staging ----
    {
        int l = tid;
        float el = El[l];
        const __nv_bfloat16* Cg = g_xcb + (long)(rowbase + l) * CONVD + COFF;
        __nv_bfloat16* dst = smy + l * 136;
#pragma unroll
        for (int n = 0; n < 128; n += 2) {
            __nv_bfloat162 cv = *(const __nv_bfloat162*)&Cg[n];
            *(__nv_bfloat162*)&dst[n] = __nv_bfloat162(
                __float2bfloat16(__bfloat162float(cv.x) * el),
                __float2bfloat16(__bfloat162float(cv.y) * el));
        }
        const float* Pv = g_prev + (long)bch * DH * DS;
        int p = tid >> 1, n0 = (tid & 1) * 64;
        __nv_bfloat16* pdst = smy + 17408 + p * 136;
#pragma unroll
        for (int n = 0; n < 64; n += 4) {
            float4 v = *(const float4*)&Pv[p * DS + n0 + n];
            __nv_bfloat162* d = (__nv_bfloat162*)&pdst[n0 + n];
            d[0] = __nv_bfloat162(__float2bfloat16(v.x), __float2bfloat16(v.y));
            d[1] = __nv_bfloat162(__float2bfloat16(v.z), __float2bfloat16(v.w));
        }
    }
    __syncthreads();

    // ---- phase 2: Y_inter ----
#pragma unroll
    for (int nt = 0; nt < 128; nt += 16) {
        uint32_t a[2][4];
#pragma unroll
        for (int mi = 0; mi < 2; mi++) {
            int arow = wid * 32 + mi * 16 + (lane & 15);
            int acol = nt + (lane >> 4) * 8;
            LDMX4(a[mi][0], a[mi][1], a[mi][2], a[mi][3], ec + (arow * 136 + acol) * 2);
        }
#pragma unroll
        for (int nb = 0; nb < 4; nb++) {
            int brow = nb * 16 + (lane & 7) + ((lane >> 4) & 1) * 8;
            int bcol = nt + ((lane >> 3) & 1) * 8;
            uint32_t t0, t1, t2, t3;
            LDMX4(t0, t1, t2, t3, pb + (brow * 136 + bcol) * 2);
            uint32_t b0[2] = {t0, t1}, b1[2] = {t2, t3};
#pragma unroll
            for (int mi = 0; mi < 2; mi++) {
                MMA16816(acc[mi][nb * 2], a[mi], b0);
                MMA16816(acc[mi][nb * 2 + 1], a[mi], b1);
            }
        }
    }

    // ---- epilogue ----
    float Dh = Dparam[h];
#pragma unroll
    for (int mi = 0; mi < 2; mi++) {
        int r = wid * 32 + mi * 16 + (lane >> 2);
#pragma unroll
        for (int nj = 0; nj < 8; nj++) {
            int cc = nj * 8 + (lane & 3) * 2;
            {
                int row = rowbase + r;
                float2 xv = *(const float2*)&g_xc[(long)row * CONVD + XOFF + h * DH + cc];
                *(float2*)&g_y[(long)row * DSSM + h * DH + cc] =
                    make_float2(acc[mi][nj][0] + Dh * xv.x, acc[mi][nj][1] + Dh * xv.y);
            }
            {
                int row = rowbase + r + 8;
                float2 xv = *(const float2*)&g_xc[(long)row * CONVD + XOFF + h * DH + cc];
                *(float2*)&g_y[(long)row * DSSM + h * DH + cc] =
                    make_float2(acc[mi][nj][2] + Dh * xv.x, acc[mi][nj][3] + Dh * xv.y);
            }
        }
    }
}

// ---------------- gate + RMSNorm, emits bf16 hi/lo ----------------
__global__ __launch_bounds__(256)
void gatenorm_kernel(const float* __restrict__ norm_w)
{
    int row = blockIdx.x;
    int tid = threadIdx.x;
    float v[8];
    float ss = 0.f;
#pragma unroll
    for (int j = 0; j < 8; j++) {
        int cidx = tid + j * 256;
        float y = g_y[(long)row * DSSM + cidx];
        float z = g_zx[(long)row * DIP + ZOFF + cidx];
        float g = z / (1.f + __expf(-z));
        float yg = y * g;
        v[j] = yg;
        ss += yg * yg;
    }
#pragma unroll
    for (int o = 16; o > 0; o >>= 1) ss += __shfl_xor_sync(0xffffffffu, ss, o);
    __shared__ float red[8];
    __shared__ float rinv;
    if ((tid & 31) == 0) red[tid >> 5] = ss;
    __syncthreads();
    if (tid == 0) {
        float t = 0.f;
#pragma unroll
        for (int i = 0; i < 8; i++) t += red[i];
        rinv = rsqrtf(t / (float)DSSM + 1e-5f);
    }
    __syncthreads();
    float r = rinv;
#pragma unroll
    for (int j = 0; j < 8; j++) {
        int cidx = tid + j * 256;
        float val = v[j] * r * norm_w[cidx];
        __nv_bfloat16 hh = __float2bfloat16(val);
        __nv_bfloat16 ll = __float2bfloat16(val - __bfloat162float(hh));
        g_yhi[(long)row * DSSM + cidx] = hh;
        g_ylo[(long)row * DSSM + cidx] = ll;
    }
}

// ---------------- host launcher ----------------
extern "C" void kernel_launch(void* const* d_in, const int* in_sizes, int n_in,
                              void* d_out, int out_size)
{
    const float* u       = (const float*)d_in[0];
    const float* W_in    = (const float*)d_in[1];
    const float* conv_w  = (const float*)d_in[2];
    const float* conv_b  = (const float*)d_in[3];
    const float* dt_bias = (const float*)d_in[4];
    const float* A_log   = (const float*)d_in[5];
    const float* Dp      = (const float*)d_in[6];
    const float* norm_w  = (const float*)d_in[7];
    const float* W_out   = (const float*)d_in[8];
    float* out = (float*)d_out;

    float *p_zx;
    cudaGetSymbolAddress((void**)&p_zx, g_zx);
    __nv_bfloat16 *p_uhi, *p_ulo, *p_w1hi, *p_w1lo, *p_yhi, *p_ylo, *p_w2hi, *p_w2lo;
    cudaGetSymbolAddress((void**)&p_uhi, g_uhi);
    cudaGetSymbolAddress((void**)&p_ulo, g_ulo);
    cudaGetSymbolAddress((void**)&p_w1hi, g_w1hi);
    cudaGetSymbolAddress((void**)&p_w1lo, g_w1lo);
    cudaGetSymbolAddress((void**)&p_yhi, g_yhi);
    cudaGetSymbolAddress((void**)&p_ylo, g_ylo);
    cudaGetSymbolAddress((void**)&p_w2hi, g_w2hi);
    cudaGetSymbolAddress((void**)&p_w2lo, g_w2lo);

    static int smem_set = 0;
    if (!smem_set) {
        cudaFuncSetAttribute(gemm_bf3, cudaFuncAttributeMaxDynamicSharedMemorySize, 2 * STAGE_ELEMS * 2);
        cudaFuncSetAttribute(cb_mma, cudaFuncAttributeMaxDynamicSharedMemorySize, 69632);
        cudaFuncSetAttribute(states_mma, cudaFuncAttributeMaxDynamicSharedMemorySize, 53248);
        cudaFuncSetAttribute(y_mma, cudaFuncAttributeMaxDynamicSharedMemorySize, 52224);
        smem_set = 1;
    }

    // 0) bf16 hi/lo conversions
    {
        long nq = (long)ROWS * DM / 4;
        cvt_split<<<(nq + 255) / 256, 256>>>(u, p_uhi, p_ulo, nq, nq);
    }
    {
        long nq = (long)DIPPAD * DM / 4, ns = (long)DIP * DM / 4;
        cvt_split<<<(nq + 255) / 256, 256>>>(W_in, p_w1hi, p_w1lo, nq, ns);
    }
    {
        long nq = (long)DM * DSSM / 4;
        cvt_split<<<(nq + 255) / 256, 256>>>(W_out, p_w2hi, p_w2lo, nq, nq);
    }

    // 1) in_proj
    gemm_bf3<<<dim3(DIPPAD / 128, ROWS / 128), 256, 2 * STAGE_ELEMS * 2>>>(
        p_uhi, p_ulo, p_w1hi, p_w1lo, p_zx, ROWS, DIP, DM, DIP);

    // 2) conv + silu
    conv_silu_kernel<<<dim3(CONVD / 256, ROWS / 32), 256>>>(conv_w, conv_b);

    // 3) dt / cumsum
    dtcum_kernel<<<BATCH * NC, 256>>>(dt_bias, A_log);

    // 4) CB
    cb_mma<<<BATCH * NC, 256, 69632>>>();

    // 5) states
    states_mma<<<BATCH * NC * NH, 128, 53248>>>();

    // 6) scan
    scan_kernel<<<BATCH * NH * 8, 256>>>();

    // 7) Y
    y_mma<<<BATCH * NC * NH, 128, 52224>>>(Dp);

    // 8) gate + RMSNorm
    gatenorm_kernel<<<ROWS, 256>>>(norm_w);

    // 9) out_proj
    gemm_bf3<<<dim3(DM / 128, ROWS / 128), 256, 2 * STAGE_ELEMS * 2>>>(
        p_yhi, p_ylo, p_w2hi, p_w2lo, out, ROWS, DM, DSSM, DM);

    (void)in_sizes; (void)n_in; (void)out_size;
}